// round 16
// baseline (speedup 1.0000x reference)
#include <cuda_runtime.h>
#include <cuda_bf16.h>

#define BB 4
#define TT 5
#define NXX 512
#define NYY 512
#define HID 64
#define NFP 4
#define PLANE (NXX*NYY)          // 262144 = 2^18
#define NPB (TT*PLANE)           // 1310720 elements per batch
#define FIELD (BB*NPB)           // 5242880

typedef unsigned long long ull;

// packed fp32x2 FMA (Blackwell-only; ptxas never auto-fuses this)
#define FMA2(d, a, b, c) \
    asm("fma.rn.f32x2 %0, %1, %2, %3;" : "=l"(d) : "l"(a), "l"(b), "l"(c))
#define PACK2(out, lo, hi) \
    asm("mov.b64 %0, {%1, %2};" : "=l"(out) : "r"(lo), "r"(hi))
#define UNPACK2(lo, hi, in) \
    asm("mov.b64 {%0, %1}, %2;" : "=r"(lo), "=r"(hi) : "l"(in))

// ---------------- scratch (static device globals; no allocation) -------------
__device__ float  g_xbuf[2][FIELD];             // ping-pong x_k  (~42 MB)
__device__ double g_acc[BB][NFP+1][2];          // cost accumulators
__device__ ull    g_pw1[1440];                  // packed W1 [45 tap][32 ocpair]
__device__ ull    g_pw2[1728];                  // packed W2 [32 cp][9 tap][6 oc]
__device__ ull    g_pb1[32];                    // packed b1 pairs

// ---------------- constant-memory weights (uniform-port loads, no crossbar) --
__constant__ ull   cw1[1440];
__constant__ ull   cw2[1728];
__constant__ ull   cb1[32];
__constant__ float cb2[5];

// ---------------- weight pre-pack (once per call graph) ----------------------
__global__ void pack_weights(const float* __restrict__ W1,
                             const float* __restrict__ b1,
                             const float* __restrict__ W2)
{
    int tid = threadIdx.x;
    for (int i = tid; i < 45*32; i += 256) {
        int q = i & 31, t = i >> 5;
        ull p;
        PACK2(p, __float_as_uint(W1[(2*q  )*45 + t]),
                 __float_as_uint(W1[(2*q+1)*45 + t]));
        g_pw1[t*32 + q] = p;
    }
    for (int i = tid; i < 32*9*6; i += 256) {
        int oc = i % 6;
        int r  = i / 6;
        int tap = r % 9;
        int cp  = r / 9;
        ull p = 0ull;
        if (oc < 5)
            PACK2(p, __float_as_uint(W2[oc*576 + (2*cp  )*9 + tap]),
                     __float_as_uint(W2[oc*576 + (2*cp+1)*9 + tap]));
        g_pw2[(cp*9 + tap)*6 + oc] = p;
    }
    if (tid < 32) {
        ull p;
        PACK2(p, __float_as_uint(b1[2*tid]), __float_as_uint(b1[2*tid+1]));
        g_pb1[tid] = p;
    }
}

// ---------------- standalone cost (row NFP only: cost of final phi output) ---
#define CGRP 163840              // NPB/4/2 groups per half
__global__ __launch_bounds__(256)
void cost_kernel(const float* __restrict__ x,
                 const float* __restrict__ gt,
                 const float* __restrict__ yobs,
                 const int*   __restrict__ mask,
                 int row)
{
    int b = blockIdx.y;
    const float* xb = x + b*NPB;
    int j0 = blockIdx.x*256 + threadIdx.x;

    float s_mse = 0.0f, s_oi = 0.0f;
    #pragma unroll
    for (int g = 0; g < 2; g++) {
        int j  = j0 + g*CGRP;
        int i  = j << 2;
        int t  = i >> 18;
        int ix = (i >> 9) & 511;
        int iy = i & 511;
        const float4 z4 = make_float4(0.f, 0.f, 0.f, 0.f);

        float4 xv = ((const float4*)xb)[j];
        float4 gv = ((const float4*)(gt   + b*NPB))[j];
        float4 yv = ((const float4*)(yobs + b*NPB))[j];
        int4   mv = ((const int4*)(mask + b*NPB))[j];
        float4 xd = (ix < NXX-1) ? ((const float4*)xb)[j + NYY/4]     : z4;
        float4 xt = (t  < TT-1)  ? ((const float4*)xb)[j + PLANE/4]   : z4;
        float nxt = (iy != NYY-4) ? xb[i + 4] : 0.0f;

        float xa[4] = {xv.x, xv.y, xv.z, xv.w};
        float ga[4] = {gv.x, gv.y, gv.z, gv.w};
        float ya[4] = {yv.x, yv.y, yv.z, yv.w};
        float ma[4] = {(float)mv.x, (float)mv.y, (float)mv.z, (float)mv.w};
        float da[4] = {xd.x, xd.y, xd.z, xd.w};
        float ta[4] = {xt.x, xt.y, xt.z, xt.w};
        float ra[4] = {xv.y, xv.z, xv.w, nxt};

        #pragma unroll
        for (int e = 0; e < 4; e++) {
            float gg = ga[e] - xa[e];
            s_mse += gg*gg;
            float d  = xa[e] - ya[e];
            float nb = ra[e] + da[e] + ta[e];
            s_oi += 1000.0f*ma[e]*d*d + 6.01f*xa[e]*xa[e] - 2.0f*xa[e]*nb;
        }
    }

    double dm = (double)s_mse, doi = (double)s_oi;
    #pragma unroll
    for (int off = 16; off; off >>= 1) {
        dm  += __shfl_down_sync(0xffffffffu, dm,  off);
        doi += __shfl_down_sync(0xffffffffu, doi, off);
    }
    __shared__ double red[2][8];
    int lane = threadIdx.x & 31, w = threadIdx.x >> 5;
    if (lane == 0) { red[0][w] = dm; red[1][w] = doi; }
    __syncthreads();
    if (threadIdx.x == 0) {
        double a = 0.0, c = 0.0;
        #pragma unroll
        for (int i2 = 0; i2 < 8; i2++) { a += red[0][i2]; c += red[1][i2]; }
        atomicAdd(&g_acc[b][row][0], a);
        atomicAdd(&g_acc[b][row][1], c);
    }
}

// ---------------- fused phi: cost(input) + conv1 -> relu -> conv2 ------------
// R13 structure (64x16 tile, 256 thr, 2 CTA/SM, 8 chunks of 8 ch), weights
// moved to __constant__: no weight traffic on the smem crossbar.
//
// smem (ull base, 67168 B):
//   shid [4 cpair][18 y][68 x-pad]      ull   39168 B
//   sin_ [5 c][20 y][70 x]              float 28000 B
#define FS_SHID  0
#define FS_ULLS  (4*18*68)
#define FS_BYTES (FS_ULLS*8 + 5*20*70*4)

__global__ __launch_bounds__(256, 2)
void fused_phi_kernel(const float* __restrict__ in,
                      const float* __restrict__ gt,
                      const float* __restrict__ yobs,
                      const int*   __restrict__ mask,
                      float* __restrict__ out,
                      int apply_mask, int cost_row)
{
    extern __shared__ __align__(16) ull smem_u[];
    ull*   shid  = smem_u + FS_SHID;
    float* sin_f = (float*)(smem_u + FS_ULLS);
    __shared__ double red[2][8];

    int b   = blockIdx.z;
    int x0  = blockIdx.x * 64;
    int y0  = blockIdx.y * 16;
    int tid = threadIdx.x;

    // ---- phase 0: input tile ----
    for (int i = tid; i < 5*20*70; i += 256) {
        int c  = i / 1400;
        int r  = i % 1400;
        int yy = r / 70;
        int xx = r % 70;
        int gy = y0 + yy - 2;
        int gx = x0 + xx - 2;
        float v = 0.0f;
        if (gy >= 0 && gy < NXX && gx >= 0 && gx < NYY)
            v = in[(size_t)(b*TT + c)*PLANE + gy*NYY + gx];
        sin_f[i] = v;
    }
    float bias2[5];
    #pragma unroll
    for (int o = 0; o < 5; o++) bias2[o] = cb2[o];

    __syncthreads();

    // ---- fused cost row (cost of the INPUT field over this tile) ----
    if (cost_row >= 0) {
        float s_mse = 0.0f, s_oi = 0.0f;
        #pragma unroll 1
        for (int e = tid; e < 5*16*64; e += 256) {      // 20 iters
            int c  = e >> 10;
            int r  = e & 1023;
            int oy = r >> 6;
            int ox = r & 63;
            const float* sp = &sin_f[(c*20 + oy + 2)*70 + ox + 2];
            float xv = sp[0];
            float xr = sp[1];
            float xd = sp[70];
            float xt = (c < TT-1) ? sp[1400] : 0.0f;

            int gi = b*NPB + c*PLANE + (y0 + oy)*NYY + x0 + ox;
            float gv = gt[gi];
            float yv = yobs[gi];
            float mv = (float)mask[gi];

            float gg = gv - xv;
            s_mse += gg*gg;
            float d  = xv - yv;
            float nb = xr + xd + xt;
            s_oi += 1000.0f*mv*d*d + 6.01f*xv*xv - 2.0f*xv*nb;
        }
        double dm = (double)s_mse, doi = (double)s_oi;
        #pragma unroll
        for (int off = 16; off; off >>= 1) {
            dm  += __shfl_down_sync(0xffffffffu, dm,  off);
            doi += __shfl_down_sync(0xffffffffu, doi, off);
        }
        int lane = tid & 31, w = tid >> 5;
        if (lane == 0) { red[0][w] = dm; red[1][w] = doi; }
        __syncthreads();
        if (tid == 0) {
            double a = 0.0, c2 = 0.0;
            #pragma unroll
            for (int i2 = 0; i2 < 8; i2++) { a += red[0][i2]; c2 += red[1][i2]; }
            atomicAdd(&g_acc[b][cost_row][0], a);
            atomicAdd(&g_acc[b][cost_row][1], c2);
        }
    }

    // conv2 output accumulators: 2 windows x 2 x-adjacent px, 5 oc
    ull acc2[4][5];
    #pragma unroll
    for (int p = 0; p < 4; p++)
        #pragma unroll
        for (int o = 0; o < 5; o++) acc2[p][o] = 0ull;

    int i2 = tid & 15;           // window base px = 2*i2 and 2*i2+32
    int oy = tid >> 4;           // 0..15

    #pragma unroll 1
    for (int ch = 0; ch < 8; ch++) {     // 8 chunks of 8 hidden channels
        __syncthreads();                  // shid free (prev phase-B done)

        // ---- phase A: conv1 -> relu -> shid (8 ch = 4 cpairs) ----
        #pragma unroll 1
        for (int u = tid; u < 396; u += 256) {
            int hy  = u / 22;             // 0..17
            int g   = u - hy*22;
            int hx0 = 3*g;                // 0..63 (covers hx 0..65)

            ull a1[3][4];
            #pragma unroll
            for (int q = 0; q < 4; q++) {
                ull bv = cb1[ch*4 + q];
                a1[0][q] = bv; a1[1][q] = bv; a1[2][q] = bv;
            }

            #pragma unroll 1
            for (int c = 0; c < TT; c++) {
                #pragma unroll
                for (int ky = 0; ky < 3; ky++) {
                    const float* row = &sin_f[(c*20 + hy + ky)*70 + hx0];
                    ull vv[5];
                    #pragma unroll
                    for (int t = 0; t < 5; t++) {
                        unsigned int bits = __float_as_uint(row[t]);
                        PACK2(vv[t], bits, bits);
                    }
                    #pragma unroll
                    for (int kx = 0; kx < 3; kx++) {
                        const ulonglong2* wq =
                            (const ulonglong2*)&cw1[(c*9 + ky*3 + kx)*32 + ch*4];
                        ulonglong2 w01 = wq[0];
                        ulonglong2 w23 = wq[1];
                        #pragma unroll
                        for (int px = 0; px < 3; px++) {
                            ull v = vv[kx + px];
                            FMA2(a1[px][0], w01.x, v, a1[px][0]);
                            FMA2(a1[px][1], w01.y, v, a1[px][1]);
                            FMA2(a1[px][2], w23.x, v, a1[px][2]);
                            FMA2(a1[px][3], w23.y, v, a1[px][3]);
                        }
                    }
                }
            }

            // store: relu; zero outside image (conv2 must see zero pad)
            int gyh = y0 + hy - 1;
            bool yok = (gyh >= 0) && (gyh < NXX);
            #pragma unroll
            for (int px = 0; px < 3; px++) {
                int hx  = hx0 + px;
                int gxh = x0 + hx - 1;
                bool ok = yok && (gxh >= 0) && (gxh < NYY);
                #pragma unroll
                for (int q = 0; q < 4; q++) {
                    unsigned int lo, hi;
                    UNPACK2(lo, hi, a1[px][q]);
                    float fl = fmaxf(__uint_as_float(lo), 0.0f);
                    float fh = fmaxf(__uint_as_float(hi), 0.0f);
                    if (!ok) { fl = 0.0f; fh = 0.0f; }
                    ull pv;
                    PACK2(pv, __float_as_uint(fl), __float_as_uint(fh));
                    shid[(q*18 + hy)*68 + hx] = pv;
                }
            }
        }
        __syncthreads();

        // ---- phase B: conv2 accumulate, 2 windows share hoisted weights ----
        #pragma unroll 1
        for (int cp = 0; cp < 4; cp++) {
            int cpg = ch*4 + cp;
            #pragma unroll
            for (int ky = 0; ky < 3; ky++) {
                const ull* wt = &cw2[(cpg*9 + ky*3)*6];
                ulonglong2 w0a = *(const ulonglong2*)&wt[0];
                ulonglong2 w0b = *(const ulonglong2*)&wt[2];
                ull        w0c = wt[4];
                ulonglong2 w1a = *(const ulonglong2*)&wt[6];
                ulonglong2 w1b = *(const ulonglong2*)&wt[8];
                ull        w1c = wt[10];
                ulonglong2 w2a = *(const ulonglong2*)&wt[12];
                ulonglong2 w2b = *(const ulonglong2*)&wt[14];
                ull        w2c = wt[16];

                const ull* rv = &shid[(cp*18 + oy + ky)*68 + 2*i2];
                #pragma unroll
                for (int wd = 0; wd < 2; wd++) {
                    const ull* rw = rv + wd*32;
                    ulonglong2 vA = *(const ulonglong2*)&rw[0];
                    ulonglong2 vB = *(const ulonglong2*)&rw[2];
                    ull v0 = vA.x, v1 = vA.y, v2 = vB.x, v3 = vB.y;
                    ull* a0  = acc2[wd*2 + 0];
                    ull* a1p = acc2[wd*2 + 1];

                    FMA2(a0[0], w0a.x, v0, a0[0]);
                    FMA2(a0[1], w0a.y, v0, a0[1]);
                    FMA2(a0[2], w0b.x, v0, a0[2]);
                    FMA2(a0[3], w0b.y, v0, a0[3]);
                    FMA2(a0[4], w0c,   v0, a0[4]);
                    FMA2(a0[0], w1a.x, v1, a0[0]);
                    FMA2(a0[1], w1a.y, v1, a0[1]);
                    FMA2(a0[2], w1b.x, v1, a0[2]);
                    FMA2(a0[3], w1b.y, v1, a0[3]);
                    FMA2(a0[4], w1c,   v1, a0[4]);
                    FMA2(a0[0], w2a.x, v2, a0[0]);
                    FMA2(a0[1], w2a.y, v2, a0[1]);
                    FMA2(a0[2], w2b.x, v2, a0[2]);
                    FMA2(a0[3], w2b.y, v2, a0[3]);
                    FMA2(a0[4], w2c,   v2, a0[4]);

                    FMA2(a1p[0], w0a.x, v1, a1p[0]);
                    FMA2(a1p[1], w0a.y, v1, a1p[1]);
                    FMA2(a1p[2], w0b.x, v1, a1p[2]);
                    FMA2(a1p[3], w0b.y, v1, a1p[3]);
                    FMA2(a1p[4], w0c,   v1, a1p[4]);
                    FMA2(a1p[0], w1a.x, v2, a1p[0]);
                    FMA2(a1p[1], w1a.y, v2, a1p[1]);
                    FMA2(a1p[2], w1b.x, v2, a1p[2]);
                    FMA2(a1p[3], w1b.y, v2, a1p[3]);
                    FMA2(a1p[4], w1c,   v2, a1p[4]);
                    FMA2(a1p[0], w2a.x, v3, a1p[0]);
                    FMA2(a1p[1], w2a.y, v3, a1p[1]);
                    FMA2(a1p[2], w2b.x, v3, a1p[2]);
                    FMA2(a1p[3], w2b.y, v3, a1p[3]);
                    FMA2(a1p[4], w2c,   v3, a1p[4]);
                }
            }
        }
    }

    // ---- epilogue: sum halves + bias, optional mask blend, write 2x2 px ----
    int oyg = y0 + oy;
    #pragma unroll
    for (int wd = 0; wd < 2; wd++) {
        int oxg  = x0 + 2*i2 + wd*32;
        int base = b*NPB + oyg*NYY + oxg;
        #pragma unroll
        for (int o = 0; o < 5; o++) {
            unsigned int lo, hi;
            UNPACK2(lo, hi, acc2[wd*2 + 0][o]);
            float r0 = __uint_as_float(lo) + __uint_as_float(hi) + bias2[o];
            UNPACK2(lo, hi, acc2[wd*2 + 1][o]);
            float r1 = __uint_as_float(lo) + __uint_as_float(hi) + bias2[o];
            int idx = base + o*PLANE;
            if (apply_mask) {
                int2   m2 = *(const int2*)&mask[idx];
                float2 y2 = *(const float2*)&yobs[idx];
                float m0 = (float)m2.x, m1 = (float)m2.y;
                r0 = r0*(1.0f - m0) + y2.x*m0;
                r1 = r1*(1.0f - m1) + y2.y*m1;
            }
            *(float2*)&out[idx] = make_float2(r0, r1);
        }
    }
}

// ---------------- finalize cmp_loss [B, NFP+1, 2] ----------------------------
__global__ void finalize_kernel(float* __restrict__ cmp)
{
    int i = threadIdx.x;
    if (i < BB*(NFP+1)*2) {
        int b = i / ((NFP+1)*2);
        int r = (i / 2) % (NFP+1);
        int c = i & 1;
        double v = g_acc[b][r][c];
        if (c == 0) v /= (double)NPB;       // mean for MSE
        cmp[i] = (float)v;
    }
}

// ---------------- launcher ---------------------------------------------------
extern "C" void kernel_launch(void* const* d_in, const int* in_sizes, int n_in,
                              void* d_out, int out_size)
{
    const float* gt   = (const float*)d_in[0];
    const float* x    = (const float*)d_in[1];
    const float* yobs = (const float*)d_in[2];
    const int*   mask = (const int*)  d_in[3];
    const float* W1   = (const float*)d_in[4];
    const float* b1   = (const float*)d_in[5];
    const float* W2   = (const float*)d_in[6];
    const float* b2   = (const float*)d_in[7];
    (void)in_sizes; (void)n_in;

    float* out     = (float*)d_out;
    float* out_x   = out;                                  // [B,5,512,512]
    float* out_cmp = out + (out_size - BB*(NFP+1)*2);      // [B,NFP+1,2]

    void *p0, *p2, *pw1, *pw2, *pb1;
    cudaGetSymbolAddress(&p0, g_xbuf);
    cudaGetSymbolAddress(&p2, g_acc);
    cudaGetSymbolAddress(&pw1, g_pw1);
    cudaGetSymbolAddress(&pw2, g_pw2);
    cudaGetSymbolAddress(&pb1, g_pb1);
    float* xb0 = (float*)p0;
    float* xb1 = xb0 + FIELD;

    cudaFuncSetAttribute(fused_phi_kernel,
                         cudaFuncAttributeMaxDynamicSharedMemorySize, FS_BYTES);

    cudaMemsetAsync(p2, 0, sizeof(double)*BB*(NFP+1)*2);
    cudaMemcpyAsync(xb0, x, sizeof(float)*FIELD, cudaMemcpyDeviceToDevice);
    pack_weights<<<1, 256>>>(W1, b1, W2);
    cudaMemcpyToSymbolAsync(cw1, pw1, sizeof(ull)*1440, 0,
                            cudaMemcpyDeviceToDevice);
    cudaMemcpyToSymbolAsync(cw2, pw2, sizeof(ull)*1728, 0,
                            cudaMemcpyDeviceToDevice);
    cudaMemcpyToSymbolAsync(cb1, pb1, sizeof(ull)*32, 0,
                            cudaMemcpyDeviceToDevice);
    cudaMemcpyToSymbolAsync(cb2, b2, sizeof(float)*5, 0,
                            cudaMemcpyDeviceToDevice);

    dim3 cgrid(CGRP/256, BB);         // (640, 4)
    dim3 gf(NYY/64, NXX/16, BB);      // (8, 32, 4) = 1024 blocks

    float* cur = xb0;
    float* nxt = xb1;
    for (int k = 0; k < NFP; k++) {
        fused_phi_kernel<<<gf, 256, FS_BYTES>>>(cur, gt, yobs, mask,
                                                nxt, 1, k);
        float* tmp = cur; cur = nxt; nxt = tmp;
    }
    // final phi (no mask blend, no fused cost), straight into d_out
    fused_phi_kernel<<<gf, 256, FS_BYTES>>>(cur, gt, yobs, mask,
                                            out_x, 0, -1);
    cost_kernel<<<cgrid, 256>>>(out_x, gt, yobs, mask, NFP);
    finalize_kernel<<<1, 64>>>(out_cmp);
}

// round 17
// speedup vs baseline: 1.2206x; 1.2206x over previous
#include <cuda_runtime.h>
#include <cuda_bf16.h>

#define BB 4
#define TT 5
#define NXX 512
#define NYY 512
#define HID 64
#define NFP 4
#define PLANE (NXX*NYY)          // 262144 = 2^18
#define NPB (TT*PLANE)           // 1310720 elements per batch
#define FIELD (BB*NPB)           // 5242880

typedef unsigned long long ull;

// packed fp32x2 FMA (Blackwell-only; ptxas never auto-fuses this)
#define FMA2(d, a, b, c) \
    asm("fma.rn.f32x2 %0, %1, %2, %3;" : "=l"(d) : "l"(a), "l"(b), "l"(c))
#define PACK2(out, lo, hi) \
    asm("mov.b64 %0, {%1, %2};" : "=l"(out) : "r"(lo), "r"(hi))
#define UNPACK2(lo, hi, in) \
    asm("mov.b64 {%0, %1}, %2;" : "=r"(lo), "=r"(hi) : "l"(in))

// ---------------- scratch (static device globals; no allocation) -------------
__device__ float  g_xbuf[2][FIELD];             // ping-pong x_k  (~42 MB)
__device__ double g_acc[BB][NFP+1][2];          // cost accumulators
__device__ ull    g_pw1[1440];                  // packed W1 [45 tap][32 ocpair]
__device__ ull    g_pw2[1728];                  // packed W2 [32 cp][9 tap][6 oc]
__device__ ull    g_pb1[32];                    // packed b1 pairs

// ---------------- weight pre-pack (once per call graph) ----------------------
__global__ void pack_weights(const float* __restrict__ W1,
                             const float* __restrict__ b1,
                             const float* __restrict__ W2)
{
    int tid = threadIdx.x;
    for (int i = tid; i < 45*32; i += 256) {
        int q = i & 31, t = i >> 5;
        ull p;
        PACK2(p, __float_as_uint(W1[(2*q  )*45 + t]),
                 __float_as_uint(W1[(2*q+1)*45 + t]));
        g_pw1[t*32 + q] = p;
    }
    for (int i = tid; i < 32*9*6; i += 256) {
        int oc = i % 6;
        int r  = i / 6;
        int tap = r % 9;
        int cp  = r / 9;
        ull p = 0ull;
        if (oc < 5)
            PACK2(p, __float_as_uint(W2[oc*576 + (2*cp  )*9 + tap]),
                     __float_as_uint(W2[oc*576 + (2*cp+1)*9 + tap]));
        g_pw2[(cp*9 + tap)*6 + oc] = p;
    }
    if (tid < 32) {
        ull p;
        PACK2(p, __float_as_uint(b1[2*tid]), __float_as_uint(b1[2*tid+1]));
        g_pb1[tid] = p;
    }
}

// ---------------- standalone cost (row NFP only: cost of final phi output) ---
#define CGRP 163840              // NPB/4/2 groups per half
__global__ __launch_bounds__(256)
void cost_kernel(const float* __restrict__ x,
                 const float* __restrict__ gt,
                 const float* __restrict__ yobs,
                 const int*   __restrict__ mask,
                 int row)
{
    int b = blockIdx.y;
    const float* xb = x + b*NPB;
    int j0 = blockIdx.x*256 + threadIdx.x;

    float s_mse = 0.0f, s_oi = 0.0f;
    #pragma unroll
    for (int g = 0; g < 2; g++) {
        int j  = j0 + g*CGRP;
        int i  = j << 2;
        int t  = i >> 18;
        int ix = (i >> 9) & 511;
        int iy = i & 511;
        const float4 z4 = make_float4(0.f, 0.f, 0.f, 0.f);

        float4 xv = ((const float4*)xb)[j];
        float4 gv = ((const float4*)(gt   + b*NPB))[j];
        float4 yv = ((const float4*)(yobs + b*NPB))[j];
        int4   mv = ((const int4*)(mask + b*NPB))[j];
        float4 xd = (ix < NXX-1) ? ((const float4*)xb)[j + NYY/4]     : z4;
        float4 xt = (t  < TT-1)  ? ((const float4*)xb)[j + PLANE/4]   : z4;
        float nxt = (iy != NYY-4) ? xb[i + 4] : 0.0f;

        float xa[4] = {xv.x, xv.y, xv.z, xv.w};
        float ga[4] = {gv.x, gv.y, gv.z, gv.w};
        float ya[4] = {yv.x, yv.y, yv.z, yv.w};
        float ma[4] = {(float)mv.x, (float)mv.y, (float)mv.z, (float)mv.w};
        float da[4] = {xd.x, xd.y, xd.z, xd.w};
        float ta[4] = {xt.x, xt.y, xt.z, xt.w};
        float ra[4] = {xv.y, xv.z, xv.w, nxt};

        #pragma unroll
        for (int e = 0; e < 4; e++) {
            float gg = ga[e] - xa[e];
            s_mse += gg*gg;
            float d  = xa[e] - ya[e];
            float nb = ra[e] + da[e] + ta[e];
            s_oi += 1000.0f*ma[e]*d*d + 6.01f*xa[e]*xa[e] - 2.0f*xa[e]*nb;
        }
    }

    double dm = (double)s_mse, doi = (double)s_oi;
    #pragma unroll
    for (int off = 16; off; off >>= 1) {
        dm  += __shfl_down_sync(0xffffffffu, dm,  off);
        doi += __shfl_down_sync(0xffffffffu, doi, off);
    }
    __shared__ double red[2][8];
    int lane = threadIdx.x & 31, w = threadIdx.x >> 5;
    if (lane == 0) { red[0][w] = dm; red[1][w] = doi; }
    __syncthreads();
    if (threadIdx.x == 0) {
        double a = 0.0, c = 0.0;
        #pragma unroll
        for (int i2 = 0; i2 < 8; i2++) { a += red[0][i2]; c += red[1][i2]; }
        atomicAdd(&g_acc[b][row][0], a);
        atomicAdd(&g_acc[b][row][1], c);
    }
}

// ---------------- fused phi: cost(input) + conv1 -> relu -> conv2 ------------
// R13 structure exactly (64x16 tile, 256 thr, 2 CTA/SM, smem weights), plus:
//  - weights loaded coalesced from pre-packed globals (pack_weights)
//  - phase-B cp-loop unrolled by 2 for LDS/FMA overlap
//
// smem partition (dynamic ull base, 92768 B total):
//   sw1  [45 tap][32 ocpair]            ull   11520 B
//   sw2  [32 cpair][9 tap][6 oc-pad]    ull   13824 B
//   shid [4 cpair][18 y][68 x-pad]      ull   39168 B
//   sb1  [32 ocpair]                    ull     256 B
//   sin_ [5 c][20 y][70 x]              float 28000 B
#define FS_SW1   0
#define FS_SW2   1440
#define FS_SHID  (FS_SW2 + 1728)
#define FS_SB1   (FS_SHID + 4*18*68)
#define FS_ULLS  (FS_SB1 + 32)
#define FS_BYTES (FS_ULLS*8 + 5*20*70*4)

__global__ __launch_bounds__(256, 2)
void fused_phi_kernel(const float* __restrict__ in,
                      const float* __restrict__ b2,   // [5]
                      const float* __restrict__ gt,
                      const float* __restrict__ yobs,
                      const int*   __restrict__ mask,
                      float* __restrict__ out,
                      int apply_mask, int cost_row)
{
    extern __shared__ __align__(16) ull smem_u[];
    ull*   sw1   = smem_u + FS_SW1;
    ull*   sw2   = smem_u + FS_SW2;
    ull*   shid  = smem_u + FS_SHID;
    ull*   sb1   = smem_u + FS_SB1;
    float* sin_f = (float*)(smem_u + FS_ULLS);
    __shared__ double red[2][8];

    int b   = blockIdx.z;
    int x0  = blockIdx.x * 64;
    int y0  = blockIdx.y * 16;
    int tid = threadIdx.x;

    // ---- phase 0: coalesced packed weights + input tile ----
    for (int i = tid; i < 1440; i += 256) sw1[i] = g_pw1[i];
    for (int i = tid; i < 1728; i += 256) sw2[i] = g_pw2[i];
    if (tid < 32) sb1[tid] = g_pb1[tid];
    for (int i = tid; i < 5*20*70; i += 256) {
        int c  = i / 1400;
        int r  = i % 1400;
        int yy = r / 70;
        int xx = r % 70;
        int gy = y0 + yy - 2;
        int gx = x0 + xx - 2;
        float v = 0.0f;
        if (gy >= 0 && gy < NXX && gx >= 0 && gx < NYY)
            v = in[(size_t)(b*TT + c)*PLANE + gy*NYY + gx];
        sin_f[i] = v;
    }
    float bias2[5];
    #pragma unroll
    for (int o = 0; o < 5; o++) bias2[o] = b2[o];

    __syncthreads();

    // ---- fused cost row (cost of the INPUT field over this tile) ----
    if (cost_row >= 0) {
        float s_mse = 0.0f, s_oi = 0.0f;
        #pragma unroll 1
        for (int e = tid; e < 5*16*64; e += 256) {      // 20 iters
            int c  = e >> 10;
            int r  = e & 1023;
            int oy = r >> 6;
            int ox = r & 63;
            const float* sp = &sin_f[(c*20 + oy + 2)*70 + ox + 2];
            float xv = sp[0];
            float xr = sp[1];
            float xd = sp[70];
            float xt = (c < TT-1) ? sp[1400] : 0.0f;

            int gi = b*NPB + c*PLANE + (y0 + oy)*NYY + x0 + ox;
            float gv = gt[gi];
            float yv = yobs[gi];
            float mv = (float)mask[gi];

            float gg = gv - xv;
            s_mse += gg*gg;
            float d  = xv - yv;
            float nb = xr + xd + xt;
            s_oi += 1000.0f*mv*d*d + 6.01f*xv*xv - 2.0f*xv*nb;
        }
        double dm = (double)s_mse, doi = (double)s_oi;
        #pragma unroll
        for (int off = 16; off; off >>= 1) {
            dm  += __shfl_down_sync(0xffffffffu, dm,  off);
            doi += __shfl_down_sync(0xffffffffu, doi, off);
        }
        int lane = tid & 31, w = tid >> 5;
        if (lane == 0) { red[0][w] = dm; red[1][w] = doi; }
        __syncthreads();
        if (tid == 0) {
            double a = 0.0, c2 = 0.0;
            #pragma unroll
            for (int i2 = 0; i2 < 8; i2++) { a += red[0][i2]; c2 += red[1][i2]; }
            atomicAdd(&g_acc[b][cost_row][0], a);
            atomicAdd(&g_acc[b][cost_row][1], c2);
        }
    }

    // conv2 output accumulators: 2 windows x 2 x-adjacent px, 5 oc
    ull acc2[4][5];
    #pragma unroll
    for (int p = 0; p < 4; p++)
        #pragma unroll
        for (int o = 0; o < 5; o++) acc2[p][o] = 0ull;

    int i2 = tid & 15;           // window base px = 2*i2 and 2*i2+32
    int oy = tid >> 4;           // 0..15

    #pragma unroll 1
    for (int ch = 0; ch < 8; ch++) {     // 8 chunks of 8 hidden channels
        __syncthreads();                  // shid free (prev phase-B done)

        // ---- phase A: conv1 -> relu -> shid (8 ch = 4 cpairs) ----
        #pragma unroll 1
        for (int u = tid; u < 396; u += 256) {
            int hy  = u / 22;             // 0..17
            int g   = u - hy*22;
            int hx0 = 3*g;                // 0..63 (covers hx 0..65)

            ull a1[3][4];
            #pragma unroll
            for (int q = 0; q < 4; q++) {
                ull bv = sb1[ch*4 + q];
                a1[0][q] = bv; a1[1][q] = bv; a1[2][q] = bv;
            }

            #pragma unroll 1
            for (int c = 0; c < TT; c++) {
                #pragma unroll
                for (int ky = 0; ky < 3; ky++) {
                    const float* row = &sin_f[(c*20 + hy + ky)*70 + hx0];
                    ull vv[5];
                    #pragma unroll
                    for (int t = 0; t < 5; t++) {
                        unsigned int bits = __float_as_uint(row[t]);
                        PACK2(vv[t], bits, bits);
                    }
                    #pragma unroll
                    for (int kx = 0; kx < 3; kx++) {
                        const ulonglong2* wq =
                            (const ulonglong2*)&sw1[(c*9 + ky*3 + kx)*32 + ch*4];
                        ulonglong2 w01 = wq[0];
                        ulonglong2 w23 = wq[1];
                        #pragma unroll
                        for (int px = 0; px < 3; px++) {
                            ull v = vv[kx + px];
                            FMA2(a1[px][0], w01.x, v, a1[px][0]);
                            FMA2(a1[px][1], w01.y, v, a1[px][1]);
                            FMA2(a1[px][2], w23.x, v, a1[px][2]);
                            FMA2(a1[px][3], w23.y, v, a1[px][3]);
                        }
                    }
                }
            }

            // store: relu; zero outside image (conv2 must see zero pad)
            int gyh = y0 + hy - 1;
            bool yok = (gyh >= 0) && (gyh < NXX);
            #pragma unroll
            for (int px = 0; px < 3; px++) {
                int hx  = hx0 + px;
                int gxh = x0 + hx - 1;
                bool ok = yok && (gxh >= 0) && (gxh < NYY);
                #pragma unroll
                for (int q = 0; q < 4; q++) {
                    unsigned int lo, hi;
                    UNPACK2(lo, hi, a1[px][q]);
                    float fl = fmaxf(__uint_as_float(lo), 0.0f);
                    float fh = fmaxf(__uint_as_float(hi), 0.0f);
                    if (!ok) { fl = 0.0f; fh = 0.0f; }
                    ull pv;
                    PACK2(pv, __float_as_uint(fl), __float_as_uint(fh));
                    shid[(q*18 + hy)*68 + hx] = pv;
                }
            }
        }
        __syncthreads();

        // ---- phase B: conv2 accumulate, 2 windows share hoisted weights ----
        #pragma unroll 2
        for (int cp = 0; cp < 4; cp++) {
            int cpg = ch*4 + cp;
            #pragma unroll
            for (int ky = 0; ky < 3; ky++) {
                const ull* wt = &sw2[(cpg*9 + ky*3)*6];
                ulonglong2 w0a = *(const ulonglong2*)&wt[0];
                ulonglong2 w0b = *(const ulonglong2*)&wt[2];
                ull        w0c = wt[4];
                ulonglong2 w1a = *(const ulonglong2*)&wt[6];
                ulonglong2 w1b = *(const ulonglong2*)&wt[8];
                ull        w1c = wt[10];
                ulonglong2 w2a = *(const ulonglong2*)&wt[12];
                ulonglong2 w2b = *(const ulonglong2*)&wt[14];
                ull        w2c = wt[16];

                const ull* rv = &shid[(cp*18 + oy + ky)*68 + 2*i2];
                #pragma unroll
                for (int wd = 0; wd < 2; wd++) {
                    const ull* rw = rv + wd*32;
                    ulonglong2 vA = *(const ulonglong2*)&rw[0];
                    ulonglong2 vB = *(const ulonglong2*)&rw[2];
                    ull v0 = vA.x, v1 = vA.y, v2 = vB.x, v3 = vB.y;
                    ull* a0  = acc2[wd*2 + 0];
                    ull* a1p = acc2[wd*2 + 1];

                    FMA2(a0[0], w0a.x, v0, a0[0]);
                    FMA2(a0[1], w0a.y, v0, a0[1]);
                    FMA2(a0[2], w0b.x, v0, a0[2]);
                    FMA2(a0[3], w0b.y, v0, a0[3]);
                    FMA2(a0[4], w0c,   v0, a0[4]);
                    FMA2(a0[0], w1a.x, v1, a0[0]);
                    FMA2(a0[1], w1a.y, v1, a0[1]);
                    FMA2(a0[2], w1b.x, v1, a0[2]);
                    FMA2(a0[3], w1b.y, v1, a0[3]);
                    FMA2(a0[4], w1c,   v1, a0[4]);
                    FMA2(a0[0], w2a.x, v2, a0[0]);
                    FMA2(a0[1], w2a.y, v2, a0[1]);
                    FMA2(a0[2], w2b.x, v2, a0[2]);
                    FMA2(a0[3], w2b.y, v2, a0[3]);
                    FMA2(a0[4], w2c,   v2, a0[4]);

                    FMA2(a1p[0], w0a.x, v1, a1p[0]);
                    FMA2(a1p[1], w0a.y, v1, a1p[1]);
                    FMA2(a1p[2], w0b.x, v1, a1p[2]);
                    FMA2(a1p[3], w0b.y, v1, a1p[3]);
                    FMA2(a1p[4], w0c,   v1, a1p[4]);
                    FMA2(a1p[0], w1a.x, v2, a1p[0]);
                    FMA2(a1p[1], w1a.y, v2, a1p[1]);
                    FMA2(a1p[2], w1b.x, v2, a1p[2]);
                    FMA2(a1p[3], w1b.y, v2, a1p[3]);
                    FMA2(a1p[4], w1c,   v2, a1p[4]);
                    FMA2(a1p[0], w2a.x, v3, a1p[0]);
                    FMA2(a1p[1], w2a.y, v3, a1p[1]);
                    FMA2(a1p[2], w2b.x, v3, a1p[2]);
                    FMA2(a1p[3], w2b.y, v3, a1p[3]);
                    FMA2(a1p[4], w2c,   v3, a1p[4]);
                }
            }
        }
    }

    // ---- epilogue: sum halves + bias, optional mask blend, write 2x2 px ----
    int oyg = y0 + oy;
    #pragma unroll
    for (int wd = 0; wd < 2; wd++) {
        int oxg  = x0 + 2*i2 + wd*32;
        int base = b*NPB + oyg*NYY + oxg;
        #pragma unroll
        for (int o = 0; o < 5; o++) {
            unsigned int lo, hi;
            UNPACK2(lo, hi, acc2[wd*2 + 0][o]);
            float r0 = __uint_as_float(lo) + __uint_as_float(hi) + bias2[o];
            UNPACK2(lo, hi, acc2[wd*2 + 1][o]);
            float r1 = __uint_as_float(lo) + __uint_as_float(hi) + bias2[o];
            int idx = base + o*PLANE;
            if (apply_mask) {
                int2   m2 = *(const int2*)&mask[idx];
                float2 y2 = *(const float2*)&yobs[idx];
                float m0 = (float)m2.x, m1 = (float)m2.y;
                r0 = r0*(1.0f - m0) + y2.x*m0;
                r1 = r1*(1.0f - m1) + y2.y*m1;
            }
            *(float2*)&out[idx] = make_float2(r0, r1);
        }
    }
}

// ---------------- finalize cmp_loss [B, NFP+1, 2] ----------------------------
__global__ void finalize_kernel(float* __restrict__ cmp)
{
    int i = threadIdx.x;
    if (i < BB*(NFP+1)*2) {
        int b = i / ((NFP+1)*2);
        int r = (i / 2) % (NFP+1);
        int c = i & 1;
        double v = g_acc[b][r][c];
        if (c == 0) v /= (double)NPB;       // mean for MSE
        cmp[i] = (float)v;
    }
}

// ---------------- launcher ---------------------------------------------------
extern "C" void kernel_launch(void* const* d_in, const int* in_sizes, int n_in,
                              void* d_out, int out_size)
{
    const float* gt   = (const float*)d_in[0];
    const float* x    = (const float*)d_in[1];
    const float* yobs = (const float*)d_in[2];
    const int*   mask = (const int*)  d_in[3];
    const float* W1   = (const float*)d_in[4];
    const float* b1   = (const float*)d_in[5];
    const float* W2   = (const float*)d_in[6];
    const float* b2   = (const float*)d_in[7];
    (void)in_sizes; (void)n_in;

    float* out     = (float*)d_out;
    float* out_x   = out;                                  // [B,5,512,512]
    float* out_cmp = out + (out_size - BB*(NFP+1)*2);      // [B,NFP+1,2]

    void *p0, *p2;
    cudaGetSymbolAddress(&p0, g_xbuf);
    cudaGetSymbolAddress(&p2, g_acc);
    float* xb0 = (float*)p0;
    float* xb1 = xb0 + FIELD;

    cudaFuncSetAttribute(fused_phi_kernel,
                         cudaFuncAttributeMaxDynamicSharedMemorySize, FS_BYTES);

    cudaMemsetAsync(p2, 0, sizeof(double)*BB*(NFP+1)*2);            // launch #0
    cudaMemcpyAsync(xb0, x, sizeof(float)*FIELD, cudaMemcpyDeviceToDevice); // #1
    pack_weights<<<1, 256>>>(W1, b1, W2);                           // launch #2

    dim3 cgrid(CGRP/256, BB);         // (640, 4)
    dim3 gf(NYY/64, NXX/16, BB);      // (8, 32, 4) = 1024 blocks

    float* cur = xb0;
    float* nxt = xb1;
    for (int k = 0; k < NFP; k++) {                                  // #3..#6
        fused_phi_kernel<<<gf, 256, FS_BYTES>>>(cur, b2, gt, yobs, mask,
                                                nxt, 1, k);          // #5 <- ncu (k=2)
        float* tmp = cur; cur = nxt; nxt = tmp;
    }
    // final phi (no mask blend, no fused cost), straight into d_out
    fused_phi_kernel<<<gf, 256, FS_BYTES>>>(cur, b2, gt, yobs, mask,
                                            out_x, 0, -1);
    cost_kernel<<<cgrid, 256>>>(out_x, gt, yobs, mask, NFP);
    finalize_kernel<<<1, 64>>>(out_cmp);
}